// round 3
// baseline (speedup 1.0000x reference)
#include <cuda_runtime.h>
#include <cstdint>

// IFOPooling: h_t = f_t * h_{t-1} + i_t * z_t over S (contiguous), per (b,h) row.
// Persistent kernel; next row staged into SMEM via cp.async (zero register cost)
// while current row (held in registers) is scanned. Each thread owns its own
// 8-element slice of the smem staging arrays -> no barriers on the staging path.

constexpr int S_LEN = 2048;
constexpr int NTHR  = 256;
constexpr int PER   = S_LEN / NTHR;   // 8 elements per thread
constexpr int OCC   = 6;
constexpr int GRID  = 152 * OCC;      // 912 persistent CTAs

__device__ __forceinline__ void cp16(uint32_t saddr, const float* gptr) {
    asm volatile("cp.async.cg.shared.global [%0], [%1], 16;\n"
                 :: "r"(saddr), "l"(gptr));
}

__global__ __launch_bounds__(NTHR, OCC)
void ifo_scan_cpasync(const float* __restrict__ f,
                      const float* __restrict__ z,
                      const float* __restrict__ i_,
                      float* __restrict__ out,
                      int n_rows)
{
    __shared__ float sf[S_LEN];
    __shared__ float sz[S_LEN];
    __shared__ float si[S_LEN];
    __shared__ float sA[NTHR / 32];
    __shared__ float sB[NTHR / 32];

    const int t    = threadIdx.x;
    const int lane = t & 31;
    const int warp = t >> 5;
    const int toff = t * PER;

    const uint32_t sfa = (uint32_t)__cvta_generic_to_shared(sf + toff);
    const uint32_t sza = (uint32_t)__cvta_generic_to_shared(sz + toff);
    const uint32_t sia = (uint32_t)__cvta_generic_to_shared(si + toff);

    int row = blockIdx.x;
    if (row >= n_rows) return;

    // ---- Prologue: stage first row ----
    {
        const size_t base = (size_t)row * S_LEN + toff;
        cp16(sfa,      f  + base);     cp16(sfa + 16, f  + base + 4);
        cp16(sza,      z  + base);     cp16(sza + 16, z  + base + 4);
        cp16(sia,      i_ + base);     cp16(sia + 16, i_ + base + 4);
        asm volatile("cp.async.commit_group;\n");
    }

    while (true) {
        const int  next     = row + GRID;
        const bool has_next = (next < n_rows);

        // ---- Wait own staged copies, pull into registers ----
        asm volatile("cp.async.wait_group 0;\n" ::: "memory");
        float4 f0 = *reinterpret_cast<const float4*>(sf + toff);
        float4 f1 = *reinterpret_cast<const float4*>(sf + toff + 4);
        float4 z0 = *reinterpret_cast<const float4*>(sz + toff);
        float4 z1 = *reinterpret_cast<const float4*>(sz + toff + 4);
        float4 i0 = *reinterpret_cast<const float4*>(si + toff);
        float4 i1 = *reinterpret_cast<const float4*>(si + toff + 4);

        // ---- Immediately kick off the next row's staging (overlaps compute) ----
        if (has_next) {
            const size_t nbase = (size_t)next * S_LEN + toff;
            cp16(sfa,      f  + nbase);     cp16(sfa + 16, f  + nbase + 4);
            cp16(sza,      z  + nbase);     cp16(sza + 16, z  + nbase + 4);
            cp16(sia,      i_ + nbase);     cp16(sia + 16, i_ + nbase + 4);
            asm volatile("cp.async.commit_group;\n");
        }

        float fv[PER] = {f0.x, f0.y, f0.z, f0.w, f1.x, f1.y, f1.z, f1.w};
        float xv[PER] = {i0.x * z0.x, i0.y * z0.y, i0.z * z0.z, i0.w * z0.w,
                         i1.x * z1.x, i1.y * z1.y, i1.z * z1.z, i1.w * z1.w};

        // ---- Local chunk -> affine pair (A, B): h_out = A*h_in + B ----
        float A = 1.0f, Bc = 0.0f;
        #pragma unroll
        for (int j = 0; j < PER; j++) {
            Bc = fmaf(fv[j], Bc, xv[j]);
            A  = A * fv[j];
        }

        // ---- Intra-warp inclusive scan over pairs ----
        float Ai = A, Bi = Bc;
        #pragma unroll
        for (int d = 1; d < 32; d <<= 1) {
            float Au = __shfl_up_sync(0xffffffffu, Ai, d);
            float Bu = __shfl_up_sync(0xffffffffu, Bi, d);
            if (lane >= d) {
                Bi = fmaf(Ai, Bu, Bi);
                Ai = Ai * Au;
            }
        }

        // ---- Cross-warp prefix via shared memory ----
        __syncthreads();   // protect sA/sB reuse across loop iterations
        if (lane == 31) { sA[warp] = Ai; sB[warp] = Bi; }
        __syncthreads();

        float Aw = 1.0f, Bw = 0.0f;
        #pragma unroll
        for (int w = 0; w < NTHR / 32; w++) {
            if (w < warp) {
                Bw = fmaf(sA[w], Bw, sB[w]);
                Aw = Aw * sA[w];
            }
        }

        // ---- Thread's exclusive prefix within warp ----
        float Ae = __shfl_up_sync(0xffffffffu, Ai, 1);
        float Be = __shfl_up_sync(0xffffffffu, Bi, 1);
        if (lane == 0) { Ae = 1.0f; Be = 0.0f; }

        // Incoming h for this chunk (h0 = 0): h_in = Ae*Bw + Be
        float h = fmaf(Ae, Bw, Be);

        // ---- Replay chunk, store ----
        float ov[PER];
        #pragma unroll
        for (int j = 0; j < PER; j++) {
            h = fmaf(fv[j], h, xv[j]);
            ov[j] = h;
        }

        const size_t obase = (size_t)row * S_LEN + toff;
        *reinterpret_cast<float4*>(out + obase)     = make_float4(ov[0], ov[1], ov[2], ov[3]);
        *reinterpret_cast<float4*>(out + obase + 4) = make_float4(ov[4], ov[5], ov[6], ov[7]);

        if (!has_next) break;
        row = next;
    }
}

extern "C" void kernel_launch(void* const* d_in, const int* in_sizes, int n_in,
                              void* d_out, int out_size)
{
    const float* f = (const float*)d_in[0];
    const float* z = (const float*)d_in[1];
    const float* i = (const float*)d_in[2];
    float* out = (float*)d_out;

    const int n_rows = in_sizes[0] / S_LEN;   // B*H = 16384
    const int grid = (n_rows < GRID) ? n_rows : GRID;
    ifo_scan_cpasync<<<grid, NTHR>>>(f, z, i, out, n_rows);
}

// round 4
// speedup vs baseline: 1.1259x; 1.1259x over previous
#include <cuda_runtime.h>

// IFOPooling: h_t = f_t * h_{t-1} + i_t * z_t over S (contiguous), per (b,h) row.
// R1 structure (one CTA per row, affine-pair parallel scan) + streaming cache
// hints: all streams have zero reuse, so evict-first loads (__ldcs) and
// streaming stores (__stcs) keep L2 from thrashing dead data.

constexpr int S_LEN  = 2048;
constexpr int NTHR   = 256;
constexpr int PER    = S_LEN / NTHR;   // 8 elements per thread

__global__ __launch_bounds__(NTHR, 8)
void ifo_scan_kernel(const float* __restrict__ f,
                     const float* __restrict__ z,
                     const float* __restrict__ i_,
                     float* __restrict__ out)
{
    const size_t row_base = (size_t)blockIdx.x * S_LEN;
    const int t    = threadIdx.x;
    const int lane = t & 31;
    const int warp = t >> 5;

    const size_t base = row_base + (size_t)t * PER;

    // ---- Load 8 contiguous elements of f, z, i (streaming / evict-first) ----
    float4 fa = __ldcs(reinterpret_cast<const float4*>(f  + base));
    float4 fb = __ldcs(reinterpret_cast<const float4*>(f  + base + 4));
    float4 za = __ldcs(reinterpret_cast<const float4*>(z  + base));
    float4 zb = __ldcs(reinterpret_cast<const float4*>(z  + base + 4));
    float4 ia = __ldcs(reinterpret_cast<const float4*>(i_ + base));
    float4 ib = __ldcs(reinterpret_cast<const float4*>(i_ + base + 4));

    float fv[PER] = {fa.x, fa.y, fa.z, fa.w, fb.x, fb.y, fb.z, fb.w};
    float xv[PER] = {ia.x * za.x, ia.y * za.y, ia.z * za.z, ia.w * za.w,
                     ib.x * zb.x, ib.y * zb.y, ib.z * zb.z, ib.w * zb.w};

    // ---- Local chunk -> affine pair (A, B): h_out = A*h_in + B ----
    float A = 1.0f, Bc = 0.0f;
    #pragma unroll
    for (int j = 0; j < PER; j++) {
        Bc = fmaf(fv[j], Bc, xv[j]);
        A  = A * fv[j];
    }

    // ---- Intra-warp inclusive scan over pairs ----
    // combine(prev=(Ap,Bp), cur=(Ac,Bc)) = (Ap*Ac, Ac*Bp + Bc)
    float Ai = A, Bi = Bc;
    #pragma unroll
    for (int d = 1; d < 32; d <<= 1) {
        float Au = __shfl_up_sync(0xffffffffu, Ai, d);
        float Bu = __shfl_up_sync(0xffffffffu, Bi, d);
        if (lane >= d) {
            Bi = fmaf(Ai, Bu, Bi);
            Ai = Ai * Au;
        }
    }

    // ---- Cross-warp prefix via shared memory (8 warps) ----
    __shared__ float sA[NTHR / 32];
    __shared__ float sB[NTHR / 32];
    if (lane == 31) { sA[warp] = Ai; sB[warp] = Bi; }
    __syncthreads();

    // Exclusive prefix over warps, computed redundantly per thread (8 iters)
    float Aw = 1.0f, Bw = 0.0f;
    #pragma unroll
    for (int w = 0; w < NTHR / 32; w++) {
        if (w < warp) {
            Bw = fmaf(sA[w], Bw, sB[w]);
            Aw = Aw * sA[w];
        }
    }

    // ---- Thread's exclusive prefix within warp ----
    float Ae = __shfl_up_sync(0xffffffffu, Ai, 1);
    float Be = __shfl_up_sync(0xffffffffu, Bi, 1);
    if (lane == 0) { Ae = 1.0f; Be = 0.0f; }

    // Combined exclusive prefix applied to h0 = 0: h_in = Ae*Bw + Be
    float h = fmaf(Ae, Bw, Be);

    // ---- Replay chunk from registers ----
    float ov[PER];
    #pragma unroll
    for (int j = 0; j < PER; j++) {
        h = fmaf(fv[j], h, xv[j]);
        ov[j] = h;
    }

    __stcs(reinterpret_cast<float4*>(out + base),
           make_float4(ov[0], ov[1], ov[2], ov[3]));
    __stcs(reinterpret_cast<float4*>(out + base + 4),
           make_float4(ov[4], ov[5], ov[6], ov[7]));
}

extern "C" void kernel_launch(void* const* d_in, const int* in_sizes, int n_in,
                              void* d_out, int out_size)
{
    const float* f = (const float*)d_in[0];
    const float* z = (const float*)d_in[1];
    const float* i = (const float*)d_in[2];
    float* out = (float*)d_out;

    const int n_rows = in_sizes[0] / S_LEN;   // B*H = 16384
    ifo_scan_kernel<<<n_rows, NTHR>>>(f, z, i, out);
}